// round 13
// baseline (speedup 1.0000x reference)
#include <cuda_runtime.h>

// StrictOrthogonal via CholeskyQR1, THREE graph nodes, ZERO software barriers.
// R4-R11 cost model: software grid barrier ~12us vs kernel-boundary sync ~3us
// -> replace both barriers with kernel boundaries. No atomics, no memset,
// fixed-order reductions everywhere (deterministic).
// R13 fix: W is 8KB (512 float4) — full copy both directions; coalesced
// warp-per-element reduce in K2.

#define M_ROWS 16384
#define R_COLS 32
#define CHUNK  128
#define NCTA   128
#define TPB    512

__device__ float  g_part[2048 * NCTA];    // transposed partials [elem][cta] (1 MB)
__device__ float2 g_W[R_COLS * R_COLS];   // W = R^{-1}, column-major (8 KB)

// ===========================================================================
// K1: stage chunk + Gram partial. 4 groups of 128 threads; group g covers
// rows [g*32, g*32+32), thread tile 2x4 of the 32x32 output. Groups 1-3 park
// partials in smem; group 0 combines (fixed order) and writes transposed.
// ===========================================================================
__global__ __launch_bounds__(TPB, 1) void k1_gram(const float2* __restrict__ A) {
    __shared__ float2 chunk[CHUNK * R_COLS];   // 32 KB
    __shared__ float  sc[3 * 2048];            // 24 KB

    const int tid = threadIdx.x;
    const int blk = blockIdx.x;

    {
        const float4* src = reinterpret_cast<const float4*>(A + (size_t)blk * CHUNK * R_COLS);
        float4* dst = reinterpret_cast<float4*>(chunk);
#pragma unroll
        for (int i = 0; i < 4; ++i) dst[tid + TPB * i] = src[tid + TPB * i];
    }
    __syncthreads();

    const int g  = tid >> 7;        // 0..3
    const int t  = tid & 127;
    const int i0 = (t & 15) * 2;
    const int j0 = (t >> 4) * 4;
    const int r0 = g * 32;

    float2 acc[2][4];
#pragma unroll
    for (int p = 0; p < 2; ++p)
#pragma unroll
        for (int q = 0; q < 4; ++q) acc[p][q] = make_float2(0.f, 0.f);

#pragma unroll 8
    for (int r = 0; r < 32; ++r) {
        const float2* rowc = &chunk[(r0 + r) * R_COLS];
        float4 av  = *reinterpret_cast<const float4*>(rowc + i0);
        float4 bv0 = *reinterpret_cast<const float4*>(rowc + j0);
        float4 bv1 = *reinterpret_cast<const float4*>(rowc + j0 + 2);
        float2 a[2] = { {av.x, av.y}, {av.z, av.w} };
        float2 b[4] = { {bv0.x, bv0.y}, {bv0.z, bv0.w}, {bv1.x, bv1.y}, {bv1.z, bv1.w} };
#pragma unroll
        for (int p = 0; p < 2; ++p)
#pragma unroll
            for (int q = 0; q < 4; ++q) {
                acc[p][q].x = fmaf(a[p].x, b[q].x, acc[p][q].x);
                acc[p][q].x = fmaf(a[p].y, b[q].y, acc[p][q].x);
                acc[p][q].y = fmaf(a[p].x, b[q].y, acc[p][q].y);
                acc[p][q].y = fmaf(-a[p].y, b[q].x, acc[p][q].y);
            }
    }
    __syncthreads();

    if (g != 0) {
#pragma unroll
        for (int p = 0; p < 2; ++p)
#pragma unroll
            for (int q = 0; q < 4; ++q) {
                int e = ((i0 + p) * R_COLS + (j0 + q)) * 2;
                sc[(g - 1) * 2048 + e]     = acc[p][q].x;
                sc[(g - 1) * 2048 + e + 1] = acc[p][q].y;
            }
    }
    __syncthreads();
    if (g == 0) {
#pragma unroll
        for (int p = 0; p < 2; ++p)
#pragma unroll
            for (int q = 0; q < 4; ++q) {
                int e = ((i0 + p) * R_COLS + (j0 + q)) * 2;
                float sx = ((acc[p][q].x + sc[e]) + sc[2048 + e]) + sc[4096 + e];
                float sy = ((acc[p][q].y + sc[e + 1]) + sc[2048 + e + 1]) + sc[4096 + e + 1];
                g_part[(e)     * NCTA + blk] = sx;
                g_part[(e + 1) * NCTA + blk] = sy;
            }
    }
}

// ===========================================================================
// K2: single CTA. Warp-per-element reduce (lane l: one coalesced float4 of
// partials 4l..4l+3; 5-level shuffle tree; 128 iterations), then warp 0 runs
// complex Cholesky + k-outer ILP trisolve; W -> global (column-major, 8 KB).
// ===========================================================================
__global__ __launch_bounds__(TPB, 1) void k2_redchol() {
    __shared__ float  sS[2048];                // reduced Gram, row-major
    __shared__ float2 LT[R_COLS * R_COLS];     // L transposed
    __shared__ float2 Wcm[R_COLS * R_COLS];    // W column-major
    __shared__ float  sinvd[R_COLS];

    const int tid = threadIdx.x;
    const int w = tid >> 5;         // 0..15
    const int l = tid & 31;

    // ---- reduce: warp w handles elements e = i*16 + w ----
#pragma unroll 4
    for (int i = 0; i < 128; ++i) {
        const int e = i * 16 + w;
        float4 v = __ldcg(reinterpret_cast<const float4*>(&g_part[(size_t)e * NCTA]) + l);
        float s = (v.x + v.y) + (v.z + v.w);
        s += __shfl_down_sync(0xffffffffu, s, 16);
        s += __shfl_down_sync(0xffffffffu, s, 8);
        s += __shfl_down_sync(0xffffffffu, s, 4);
        s += __shfl_down_sync(0xffffffffu, s, 2);
        s += __shfl_down_sync(0xffffffffu, s, 1);
        if (l == 0) sS[e] = s;
    }
    __syncthreads();

    // ---- warp 0: Cholesky + trisolve ----
    if (tid < 32) {
        const unsigned FULL = 0xffffffffu;
        const int r = tid;

        float2 row[R_COLS];
#pragma unroll
        for (int c = 0; c < R_COLS; ++c) {
            row[c].x = sS[(r * R_COLS + c) * 2];
            row[c].y = sS[(r * R_COLS + c) * 2 + 1];
        }

#pragma unroll
        for (int k = 0; k < R_COLS; ++k) {
            float dkk  = __shfl_sync(FULL, row[k].x, k);
            float invs = rsqrtf(dkk);
            float2 lv;
            lv.x = row[k].x * invs;
            lv.y = row[k].y * invs;
            row[k] = lv;
#pragma unroll
            for (int j = k + 1; j < R_COLS; ++j) {
                float lx = __shfl_sync(FULL, lv.x, j);
                float ly = __shfl_sync(FULL, lv.y, j);
                row[j].x -= lv.x * lx + lv.y * ly;
                row[j].y -= lv.y * lx - lv.x * ly;
            }
        }

#pragma unroll
        for (int k = 0; k < R_COLS; ++k)
            if (k <= r) LT[k * R_COLS + r] = row[k];
        __syncwarp();
        sinvd[r] = 1.0f / LT[r * R_COLS + r].x;
        __syncwarp();

        float2 s[R_COLS];
#pragma unroll
        for (int j = 0; j < R_COLS; ++j)
            s[j] = (j == r) ? make_float2(1.f, 0.f) : make_float2(0.f, 0.f);

#pragma unroll
        for (int k = 0; k < R_COLS; ++k) {
            float dk = sinvd[k];
            s[k].x *= dk;
            s[k].y *= dk;
#pragma unroll
            for (int j = k + 1; j < R_COLS; ++j) {
                float2 lv = LT[k * R_COLS + j];
                s[j].x -= lv.x * s[k].x - lv.y * s[k].y;
                s[j].y -= lv.x * s[k].y + lv.y * s[k].x;
            }
        }

        // W[c][j] = conj(x[j]) -> col-major Wcm[j*32 + c]; exact 0 for j < c.
#pragma unroll
        for (int j = 0; j < R_COLS; ++j)
            Wcm[j * R_COLS + r] = make_float2(s[j].x, -s[j].y);
    }
    __syncthreads();

    // ---- write W to global: 512 float4 over 512 threads (FULL 8 KB) ----
    reinterpret_cast<float4*>(g_W)[tid] =
        reinterpret_cast<const float4*>(Wcm)[tid];
}

// ===========================================================================
// K3: apply. Load W (col-major, full 8 KB) to smem, stage chunk, 4 threads
// per row apply (stride-4 columns), store directly to Out.
// ===========================================================================
__global__ __launch_bounds__(TPB, 1) void k3_apply(const float2* __restrict__ A,
                                                   float2* __restrict__ Out) {
    __shared__ float2 chunk[CHUNK * R_COLS];   // 32 KB
    __shared__ float2 Wcm[R_COLS * R_COLS];    // 8 KB

    const int tid = threadIdx.x;
    const int blk = blockIdx.x;

    // Full W: 512 float4 over 512 threads.
    reinterpret_cast<float4*>(Wcm)[tid] =
        __ldcg(reinterpret_cast<const float4*>(g_W) + tid);
    {
        const float4* src = reinterpret_cast<const float4*>(A + (size_t)blk * CHUNK * R_COLS);
        float4* dst = reinterpret_cast<float4*>(chunk);
#pragma unroll
        for (int i = 0; i < 4; ++i) dst[tid + TPB * i] = src[tid + TPB * i];
    }
    __syncthreads();

    const int row = tid >> 2;       // 0..127
    const int c0  = tid & 3;

    float2 a[R_COLS];
    {
        const float4* rp = reinterpret_cast<const float4*>(&chunk[row * R_COLS]);
#pragma unroll
        for (int i = 0; i < 16; ++i) {
            float4 v = rp[i];
            a[2 * i]     = make_float2(v.x, v.y);
            a[2 * i + 1] = make_float2(v.z, v.w);
        }
    }

    float2* outr = Out + ((size_t)blk * CHUNK + row) * R_COLS;
#pragma unroll
    for (int jj = 0; jj < 8; ++jj) {
        const int j = 4 * jj + c0;
        const float2* wj = &Wcm[j * R_COLS];
        float2 s = make_float2(0.f, 0.f);
#pragma unroll
        for (int i = 0; i < R_COLS; ++i) {
            if (i <= 4 * jj + 3) {          // compile-time prune of tail
                if (i <= j) {               // runtime triangular guard
                    float2 w = wj[i];
                    s.x = fmaf(a[i].x, w.x, s.x);
                    s.x = fmaf(-a[i].y, w.y, s.x);
                    s.y = fmaf(a[i].x, w.y, s.y);
                    s.y = fmaf(a[i].y, w.x, s.y);
                }
            }
        }
        outr[j] = s;                        // direct global store
    }
}

// ---------------------------------------------------------------------------
extern "C" void kernel_launch(void* const* d_in, const int* in_sizes, int n_in,
                              void* d_out, int out_size) {
    (void)in_sizes; (void)n_in; (void)out_size;
    const float2* A = reinterpret_cast<const float2*>(d_in[0]);
    float2* Out = reinterpret_cast<float2*>(d_out);

    k1_gram<<<NCTA, TPB>>>(A);
    k2_redchol<<<1, TPB>>>();
    k3_apply<<<NCTA, TPB>>>(A, Out);
}

// round 15
// speedup vs baseline: 1.4044x; 1.4044x over previous
#include <cuda_runtime.h>

// StrictOrthogonal via CholeskyQR1, persistent kernel, ONE graph node.
// R15: self-resetting grid barrier (each CTA zeroes the SIBLING counter
// before arriving; all resets are fenced before any arrival, and no CTA can
// pass until all arrived -> race-free, state restored for next graph replay).
// Removes the cudaMemsetAsync node. Structure = R9 best (42.7us):
// [stage+gram] bar0 [reduce] bar1 [cholinv -> apply -> direct store].
// 128 CTAs x 512 threads, all co-resident -> grid barrier safe.

#define M_ROWS 16384
#define R_COLS 32
#define CHUNK  128
#define NCTA   128
#define TPB    512

__device__ float    g_part[2048 * NCTA];   // transposed partials [elem][cta] (1 MB)
__device__ float2   g_S[R_COLS * R_COLS];  // reduced Gram
__device__ unsigned g_bar[2];              // zero-initialized device globals

// ---------------------------------------------------------------------------
// Self-resetting grid barrier. Counters alternate: barrier `id` resets
// counter `1-id` pre-arrival. First launch: both 0 (static init). After a
// full launch (bar0 then bar1): c0 = 0 (reset during bar1), c1 = NCTA
// (reset during next launch's bar0, before any CTA can re-arrive at bar1).
// ---------------------------------------------------------------------------
__device__ __forceinline__ void grid_barrier(int id) {
    __syncthreads();                        // CTA done with prior phase
    if (threadIdx.x == 0) {
        g_bar[1 - id] = 0;                  // idempotent sibling reset
        __threadfence();                    // order reset + phase writes
        atomicAdd(&g_bar[id], 1u);
        volatile unsigned* p = &g_bar[id];
        while (*p < NCTA) __nanosleep(32);
        __threadfence();
    }
    __syncthreads();
}

// ---------------------------------------------------------------------------
// Gram partial: 4 groups of 128 threads, group g covers rows [g*32,g*32+32),
// thread tile 2x4 of the 32x32 output. Groups 1-3 park partials in smem;
// group 0 combines (fixed order) and writes TRANSPOSED to g_part[e][blk].
// ---------------------------------------------------------------------------
__device__ __forceinline__ void gram_phase(const float2* __restrict__ chunk,
                                           float* __restrict__ sc, int blk) {
    const int tid = threadIdx.x;
    const int g  = tid >> 7;        // 0..3
    const int t  = tid & 127;
    const int i0 = (t & 15) * 2;
    const int j0 = (t >> 4) * 4;
    const int r0 = g * 32;

    float2 acc[2][4];
#pragma unroll
    for (int p = 0; p < 2; ++p)
#pragma unroll
        for (int q = 0; q < 4; ++q) acc[p][q] = make_float2(0.f, 0.f);

#pragma unroll 8
    for (int r = 0; r < 32; ++r) {
        const float2* rowc = &chunk[(r0 + r) * R_COLS];
        float4 av  = *reinterpret_cast<const float4*>(rowc + i0);
        float4 bv0 = *reinterpret_cast<const float4*>(rowc + j0);
        float4 bv1 = *reinterpret_cast<const float4*>(rowc + j0 + 2);
        float2 a[2] = { {av.x, av.y}, {av.z, av.w} };
        float2 b[4] = { {bv0.x, bv0.y}, {bv0.z, bv0.w}, {bv1.x, bv1.y}, {bv1.z, bv1.w} };
#pragma unroll
        for (int p = 0; p < 2; ++p)
#pragma unroll
            for (int q = 0; q < 4; ++q) {
                acc[p][q].x = fmaf(a[p].x, b[q].x, acc[p][q].x);
                acc[p][q].x = fmaf(a[p].y, b[q].y, acc[p][q].x);
                acc[p][q].y = fmaf(a[p].x, b[q].y, acc[p][q].y);
                acc[p][q].y = fmaf(-a[p].y, b[q].x, acc[p][q].y);
            }
    }
    __syncthreads();

    if (g != 0) {
#pragma unroll
        for (int p = 0; p < 2; ++p)
#pragma unroll
            for (int q = 0; q < 4; ++q) {
                int e = ((i0 + p) * R_COLS + (j0 + q)) * 2;
                sc[(g - 1) * 2048 + e]     = acc[p][q].x;
                sc[(g - 1) * 2048 + e + 1] = acc[p][q].y;
            }
    }
    __syncthreads();
    if (g == 0) {
#pragma unroll
        for (int p = 0; p < 2; ++p)
#pragma unroll
            for (int q = 0; q < 4; ++q) {
                int e = ((i0 + p) * R_COLS + (j0 + q)) * 2;
                float sx = ((acc[p][q].x + sc[e]) + sc[2048 + e]) + sc[4096 + e];
                float sy = ((acc[p][q].y + sc[e + 1]) + sc[2048 + e + 1]) + sc[4096 + e + 1];
                g_part[(e)     * NCTA + blk] = sx;
                g_part[(e + 1) * NCTA + blk] = sy;
            }
    }
}

// ---------------------------------------------------------------------------
// Reduce: element e = blk*16 + warp (16 warps). Lane l: one coalesced float4
// (partials 4l..4l+3), then 5-level shuffle tree. Fixed order -> deterministic.
// ---------------------------------------------------------------------------
__device__ __forceinline__ void reduce_phase(int blk) {
    const int w = threadIdx.x >> 5;     // 0..15
    const int l = threadIdx.x & 31;
    const int e = blk * 16 + w;
    float4 v = __ldcg(reinterpret_cast<const float4*>(&g_part[(size_t)e * NCTA]) + l);
    float s = (v.x + v.y) + (v.z + v.w);
    s += __shfl_down_sync(0xffffffffu, s, 16);
    s += __shfl_down_sync(0xffffffffu, s, 8);
    s += __shfl_down_sync(0xffffffffu, s, 4);
    s += __shfl_down_sync(0xffffffffu, s, 2);
    s += __shfl_down_sync(0xffffffffu, s, 1);
    if (l == 0) reinterpret_cast<float*>(g_S)[e] = s;
}

// ---------------------------------------------------------------------------
// Warp 0: complex Cholesky of g_S (lane r = row r), L stored transposed in
// smem, diag reciprocals precomputed, k-outer ILP trisolve (lane c = column c
// of L^{-1}); W = R^{-1} written col-major (exact zeros below diagonal).
// ---------------------------------------------------------------------------
__device__ __forceinline__ void cholinv_phase(float2* __restrict__ LT,
                                              float2* __restrict__ Wcm,
                                              float* __restrict__ sinvd) {
    const unsigned FULL = 0xffffffffu;
    const int r = threadIdx.x;

    float2 row[R_COLS];
#pragma unroll
    for (int c = 0; c < R_COLS; ++c) row[c] = __ldcg(&g_S[r * R_COLS + c]);

#pragma unroll
    for (int k = 0; k < R_COLS; ++k) {
        float dkk  = __shfl_sync(FULL, row[k].x, k);
        float invs = rsqrtf(dkk);
        float2 lv;
        lv.x = row[k].x * invs;
        lv.y = row[k].y * invs;
        row[k] = lv;
#pragma unroll
        for (int j = k + 1; j < R_COLS; ++j) {
            float lx = __shfl_sync(FULL, lv.x, j);
            float ly = __shfl_sync(FULL, lv.y, j);
            row[j].x -= lv.x * lx + lv.y * ly;
            row[j].y -= lv.y * lx - lv.x * ly;
        }
    }

#pragma unroll
    for (int k = 0; k < R_COLS; ++k)
        if (k <= r) LT[k * R_COLS + r] = row[k];
    __syncwarp();
    sinvd[r] = 1.0f / LT[r * R_COLS + r].x;
    __syncwarp();

    float2 s[R_COLS];
#pragma unroll
    for (int j = 0; j < R_COLS; ++j)
        s[j] = (j == r) ? make_float2(1.f, 0.f) : make_float2(0.f, 0.f);

#pragma unroll
    for (int k = 0; k < R_COLS; ++k) {
        float dk = sinvd[k];
        s[k].x *= dk;
        s[k].y *= dk;
#pragma unroll
        for (int j = k + 1; j < R_COLS; ++j) {
            float2 lv = LT[k * R_COLS + j];
            s[j].x -= lv.x * s[k].x - lv.y * s[k].y;
            s[j].y -= lv.x * s[k].y + lv.y * s[k].x;
        }
    }

    // W[c][j] = conj(x[j]) -> col-major Wcm[j*32 + c]; exact 0 for j < c.
#pragma unroll
    for (int j = 0; j < R_COLS; ++j)
        Wcm[j * R_COLS + r] = make_float2(s[j].x, -s[j].y);
}

// ---------------------------------------------------------------------------
__global__ __launch_bounds__(TPB, 1) void fused_cholqr1(const float2* __restrict__ A,
                                                        float2* __restrict__ Out) {
    __shared__ float2 chunk[CHUNK * R_COLS];   // 32 KB resident rows
    __shared__ float  sc[3 * 2048];            // 24 KB gram bufs / LT / Wcm
    __shared__ float  sinvd[R_COLS];

    const int tid = threadIdx.x;
    const int blk = blockIdx.x;

    // Stage chunk (only read of A): 2048 float4 over 512 threads.
    {
        const float4* src = reinterpret_cast<const float4*>(A + (size_t)blk * CHUNK * R_COLS);
        float4* dst = reinterpret_cast<float4*>(chunk);
#pragma unroll
        for (int i = 0; i < 4; ++i) dst[tid + TPB * i] = src[tid + TPB * i];
    }
    __syncthreads();

    gram_phase(chunk, sc, blk);
    grid_barrier(0);
    reduce_phase(blk);
    grid_barrier(1);

    float2* LT  = reinterpret_cast<float2*>(sc);          // 8 KB
    float2* Wcm = reinterpret_cast<float2*>(sc + 2048);   // 8 KB

    if (tid < 32) cholinv_phase(LT, Wcm, sinvd);
    __syncthreads();                // Wcm ready

    // Apply + direct store: 4 threads per row, stride-4 columns.
    const int row = tid >> 2;       // 0..127
    const int c0  = tid & 3;

    float2 a[R_COLS];
    {
        const float4* rp = reinterpret_cast<const float4*>(&chunk[row * R_COLS]);
#pragma unroll
        for (int i = 0; i < 16; ++i) {
            float4 v = rp[i];
            a[2 * i]     = make_float2(v.x, v.y);
            a[2 * i + 1] = make_float2(v.z, v.w);
        }
    }

    float2* outr = Out + ((size_t)blk * CHUNK + row) * R_COLS;
#pragma unroll
    for (int jj = 0; jj < 8; ++jj) {
        const int j = 4 * jj + c0;
        const float2* wj = &Wcm[j * R_COLS];
        float2 s = make_float2(0.f, 0.f);
#pragma unroll
        for (int i = 0; i < R_COLS; ++i) {
            if (i <= 4 * jj + 3) {          // compile-time prune of tail
                if (i <= j) {               // runtime triangular guard
                    float2 w = wj[i];
                    s.x = fmaf(a[i].x, w.x, s.x);
                    s.x = fmaf(-a[i].y, w.y, s.x);
                    s.y = fmaf(a[i].x, w.y, s.y);
                    s.y = fmaf(a[i].y, w.x, s.y);
                }
            }
        }
        outr[j] = s;                        // direct global store
    }
}

// ---------------------------------------------------------------------------
extern "C" void kernel_launch(void* const* d_in, const int* in_sizes, int n_in,
                              void* d_out, int out_size) {
    (void)in_sizes; (void)n_in; (void)out_size;
    const float2* A = reinterpret_cast<const float2*>(d_in[0]);
    float2* Out = reinterpret_cast<float2*>(d_out);

    fused_cholqr1<<<NCTA, TPB>>>(A, Out);   // single graph node
}